// round 16
// baseline (speedup 1.0000x reference)
#include <cuda_runtime.h>
#include <cstdint>

#define NUM_USERS 100000
#define NUM_ITEMS 150000
#define N_NODES   250000
#define DIM       64
#define N_EDGES   2000000
#define EPS_F     0.2f

#define SCAN_B    512
#define N_SCAN_BLK ((N_NODES + SCAN_B - 1) / SCAN_B)   // 489

// ---------------------------------------------------------------------------
// Device scratch (allocation-free, graph-capturable)
// ---------------------------------------------------------------------------
__device__ unsigned g_cnt[N_NODES];        // in-degree per node (build only)
__device__ unsigned g_off[N_NODES + 1];    // CSR row starts (exclusive scan, +sentinel)
__device__ unsigned g_cur[N_NODES];        // fill cursors
__device__ unsigned g_bsum[SCAN_B];        // block sums for the scan
__device__ uint2    g_edges[N_EDGES];      // dst-sorted: {src, val_bits}
__device__ float    g_A[(size_t)N_NODES * DIM];  // x0
__device__ float    g_B[(size_t)N_NODES * DIM];  // x1

// L2-only load (no L1 allocation) for low-reuse random gathers
__device__ __forceinline__ float4 ldcg4(const float4* p) {
    float4 r;
    asm volatile("ld.global.cg.v4.f32 {%0, %1, %2, %3}, [%4];"
                 : "=f"(r.x), "=f"(r.y), "=f"(r.z), "=f"(r.w) : "l"(p));
    return r;
}

// ---------------------------------------------------------------------------
// CSR build
// ---------------------------------------------------------------------------
__global__ void zero_cnt_k() {
    unsigned i = blockIdx.x * blockDim.x + threadIdx.x;
    if (i < N_NODES) { g_cnt[i] = 0u; }
}

__global__ void hist_k(const int* __restrict__ dst) {
    unsigned g = blockIdx.x * blockDim.x + threadIdx.x;
    if (g >= (unsigned)(N_EDGES / 4)) return;
    int4 d4 = __ldg(reinterpret_cast<const int4*>(dst) + g);
    atomicAdd(&g_cnt[d4.x], 1u);
    atomicAdd(&g_cnt[d4.y], 1u);
    atomicAdd(&g_cnt[d4.z], 1u);
    atomicAdd(&g_cnt[d4.w], 1u);
}

__global__ void scan1_k() {
    __shared__ unsigned sm[SCAN_B];
    unsigned i = blockIdx.x * SCAN_B + threadIdx.x;
    unsigned v = (i < N_NODES) ? g_cnt[i] : 0u;
    sm[threadIdx.x] = v;
    __syncthreads();
    for (int ofs = 1; ofs < SCAN_B; ofs <<= 1) {
        unsigned add = (threadIdx.x >= (unsigned)ofs) ? sm[threadIdx.x - ofs] : 0u;
        __syncthreads();
        sm[threadIdx.x] += add;
        __syncthreads();
    }
    unsigned incl = sm[threadIdx.x];
    if (i < N_NODES) g_off[i] = incl - v;            // exclusive within block
    if (threadIdx.x == SCAN_B - 1) g_bsum[blockIdx.x] = incl;
}

__global__ void scan2_k() {
    __shared__ unsigned sm[SCAN_B];
    unsigned v = (threadIdx.x < N_SCAN_BLK) ? g_bsum[threadIdx.x] : 0u;
    sm[threadIdx.x] = v;
    __syncthreads();
    for (int ofs = 1; ofs < SCAN_B; ofs <<= 1) {
        unsigned add = (threadIdx.x >= (unsigned)ofs) ? sm[threadIdx.x - ofs] : 0u;
        __syncthreads();
        sm[threadIdx.x] += add;
        __syncthreads();
    }
    if (threadIdx.x < N_SCAN_BLK) g_bsum[threadIdx.x] = sm[threadIdx.x] - v;  // exclusive
}

__global__ void scan3_k() {
    unsigned i = blockIdx.x * blockDim.x + threadIdx.x;
    if (i >= N_NODES) return;
    unsigned val = g_off[i] + g_bsum[i / SCAN_B];
    g_off[i] = val;
    g_cur[i] = val;
    if (i == 0) g_off[N_NODES] = (unsigned)N_EDGES;   // sentinel
}

__global__ void fill_k(const int* __restrict__ src,
                       const int* __restrict__ dst,
                       const float* __restrict__ vals) {
    unsigned g = blockIdx.x * blockDim.x + threadIdx.x;
    if (g >= (unsigned)(N_EDGES / 4)) return;
    int4   s4 = __ldg(reinterpret_cast<const int4*>(src) + g);
    int4   d4 = __ldg(reinterpret_cast<const int4*>(dst) + g);
    float4 v4 = __ldg(reinterpret_cast<const float4*>(vals) + g);
    unsigned p0 = atomicAdd(&g_cur[d4.x], 1u);
    unsigned p1 = atomicAdd(&g_cur[d4.y], 1u);
    unsigned p2 = atomicAdd(&g_cur[d4.z], 1u);
    unsigned p3 = atomicAdd(&g_cur[d4.w], 1u);
    g_edges[p0] = make_uint2((unsigned)s4.x, __float_as_uint(v4.x));
    g_edges[p1] = make_uint2((unsigned)s4.y, __float_as_uint(v4.y));
    g_edges[p2] = make_uint2((unsigned)s4.z, __float_as_uint(v4.z));
    g_edges[p3] = make_uint2((unsigned)s4.w, __float_as_uint(v4.w));
}

// ---------------------------------------------------------------------------
// Fused layer kernels: gather-reduce + noise perturbation (+ cl / final)
// 16 lanes per node, one float4 column each; unroll-4 over in-edges for MLP.
// Cache policy: row gathers = ld.global.cg (L2-only; the 64MB table is the
// only structure with reuse). ALL single-use streams (edge records, noise,
// outputs) = evict-first (.cs), maximizing L2 residency for the gathers.
//   K=0: x0 = f(segsum(E), noise0); A := x0; cl_out = l2norm(x0)
//   K=1: x1 = f(segsum(A), noise1); B := x1
//   K=2: x2 = f(segsum(B), noise2); out = l2norm((e0 + A + B + x2) * 0.25)
// ---------------------------------------------------------------------------
__device__ __forceinline__ float halfwarp_sum(float ss) {
    ss += __shfl_xor_sync(0xffffffffu, ss, 1);
    ss += __shfl_xor_sync(0xffffffffu, ss, 2);
    ss += __shfl_xor_sync(0xffffffffu, ss, 4);
    ss += __shfl_xor_sync(0xffffffffu, ss, 8);
    return ss;
}

__device__ __forceinline__ uint2 ldcs_edge(const uint2* p) {
    uint2 r;
    asm volatile("ld.global.cs.v2.u32 {%0, %1}, [%2];"
                 : "=r"(r.x), "=r"(r.y) : "l"(p));
    return r;
}

template <int K>
__device__ __forceinline__ const float4* src_row(
        unsigned node, const float4* __restrict__ ue, const float4* __restrict__ ie)
{
    if (K == 0) {
        return (node < NUM_USERS) ? (ue + (size_t)node * 16)
                                  : (ie + (size_t)(node - NUM_USERS) * 16);
    }
    const float* b = (K == 1) ? g_A : g_B;
    return reinterpret_cast<const float4*>(b) + (size_t)node * 16;
}

template <int K>
__global__ void __launch_bounds__(256) layer_k(
        const float* __restrict__ noise_k,
        const float4* __restrict__ ue,
        const float4* __restrict__ ie,
        float4* __restrict__ out,      // K==2
        float4* __restrict__ cl_out)   // K==0
{
    unsigned t = blockIdx.x * blockDim.x + threadIdx.x;
    if (t >= (unsigned)N_NODES * 16u) return;
    unsigned node = t >> 4;
    unsigned c = t & 15u;

    unsigned base = __ldg(&g_off[node]);
    unsigned end  = __ldg(&g_off[node + 1]);
    unsigned deg  = end - base;

    float4 s = make_float4(0.f, 0.f, 0.f, 0.f);

    // unroll-4 main loop: 4 independent gathers in flight
    unsigned i = 0;
    for (; i + 4 <= deg; i += 4) {
        uint2 e0 = ldcs_edge(&g_edges[base + i]);
        uint2 e1 = ldcs_edge(&g_edges[base + i + 1]);
        uint2 e2 = ldcs_edge(&g_edges[base + i + 2]);
        uint2 e3 = ldcs_edge(&g_edges[base + i + 3]);
        float4 x0 = ldcg4(src_row<K>(e0.x, ue, ie) + c);
        float4 x1 = ldcg4(src_row<K>(e1.x, ue, ie) + c);
        float4 x2 = ldcg4(src_row<K>(e2.x, ue, ie) + c);
        float4 x3 = ldcg4(src_row<K>(e3.x, ue, ie) + c);
        float v0 = __uint_as_float(e0.y), v1 = __uint_as_float(e1.y);
        float v2 = __uint_as_float(e2.y), v3 = __uint_as_float(e3.y);
        s.x += v0 * x0.x + v1 * x1.x + v2 * x2.x + v3 * x3.x;
        s.y += v0 * x0.y + v1 * x1.y + v2 * x2.y + v3 * x3.y;
        s.z += v0 * x0.z + v1 * x1.z + v2 * x2.z + v3 * x3.z;
        s.w += v0 * x0.w + v1 * x1.w + v2 * x2.w + v3 * x3.w;
    }
    for (; i < deg; i++) {
        uint2 e = ldcs_edge(&g_edges[base + i]);
        float4 x = ldcg4(src_row<K>(e.x, ue, ie) + c);
        float v = __uint_as_float(e.y);
        s.x += v * x.x; s.y += v * x.y; s.z += v * x.z; s.w += v * x.w;
    }

    // noise perturbation
    float4 n4 = __ldcs(reinterpret_cast<const float4*>(noise_k) + t);
    float ss = halfwarp_sum(n4.x * n4.x + n4.y * n4.y + n4.z * n4.z + n4.w * n4.w);
    float scale = rsqrtf(fmaxf(ss, 1e-24f)) * EPS_F;

    float4 x = s;
    x.x += (float)((s.x > 0.f) - (s.x < 0.f)) * n4.x * scale;
    x.y += (float)((s.y > 0.f) - (s.y < 0.f)) * n4.y * scale;
    x.z += (float)((s.z > 0.f) - (s.z < 0.f)) * n4.z * scale;
    x.w += (float)((s.w > 0.f) - (s.w < 0.f)) * n4.w * scale;

    if (K == 2) {
        // fused final: out = l2norm((e0 + x0 + x1 + x2) * 0.25)
        float4 e0 = (node < NUM_USERS)
            ? __ldg(ue + (size_t)node * 16 + c)
            : __ldg(ie + (size_t)(node - NUM_USERS) * 16 + c);
        float4 a0 = reinterpret_cast<const float4*>(g_A)[t];
        float4 a1 = reinterpret_cast<const float4*>(g_B)[t];
        float4 a;
        a.x = (e0.x + a0.x + a1.x + x.x) * 0.25f;
        a.y = (e0.y + a0.y + a1.y + x.y) * 0.25f;
        a.z = (e0.z + a0.z + a1.z + x.z) * 0.25f;
        a.w = (e0.w + a0.w + a1.w + x.w) * 0.25f;
        float s2 = halfwarp_sum(a.x * a.x + a.y * a.y + a.z * a.z + a.w * a.w);
        float inv = rsqrtf(fmaxf(s2, 1e-24f));
        a.x *= inv; a.y *= inv; a.z *= inv; a.w *= inv;
        __stcs(out + t, a);
        return;
    }

    float4* tgt = (K == 0) ? reinterpret_cast<float4*>(g_A)
                           : reinterpret_cast<float4*>(g_B);
    tgt[t] = x;

    if (K == 0) {
        float s2 = halfwarp_sum(x.x * x.x + x.y * x.y + x.z * x.z + x.w * x.w);
        float inv = rsqrtf(fmaxf(s2, 1e-24f));
        x.x *= inv; x.y *= inv; x.z *= inv; x.w *= inv;
        __stcs(cl_out + t, x);
    }
}

extern "C" void kernel_launch(void* const* d_in, const int* in_sizes, int n_in,
                              void* d_out, int out_size) {
    const float* user_emb = (const float*)d_in[0];
    const float* item_emb = (const float*)d_in[1];
    const float* vals     = (const float*)d_in[2];
    const float* noise    = (const float*)d_in[3];
    const int*   src      = (const int*)d_in[4];
    const int*   dst      = (const int*)d_in[5];
    float4* out    = (float4*)d_out;
    float4* cl_out = (float4*)((float*)d_out + (size_t)N_NODES * DIM);
    const float4* ue4 = (const float4*)user_emb;
    const float4* ie4 = (const float4*)item_emb;

    const int TB = 256;
    const int node_blk  = (N_NODES + TB - 1) / TB;                 // 977
    const int edge4_blk = (N_EDGES / 4 + TB - 1) / TB;             // 1954
    const int work_blk  = ((unsigned)N_NODES * 16u + TB - 1) / TB; // 15625

    // CSR build
    zero_cnt_k<<<node_blk, TB>>>();
    hist_k<<<edge4_blk, TB>>>(dst);
    scan1_k<<<N_SCAN_BLK, SCAN_B>>>();
    scan2_k<<<1, SCAN_B>>>();
    scan3_k<<<node_blk, TB>>>();
    fill_k<<<edge4_blk, TB>>>(src, dst, vals);

    // fused layers
    layer_k<0><<<work_blk, TB>>>(noise,                              ue4, ie4, out, cl_out);
    layer_k<1><<<work_blk, TB>>>(noise + (size_t)N_NODES * DIM,      ue4, ie4, out, cl_out);
    layer_k<2><<<work_blk, TB>>>(noise + 2 * (size_t)N_NODES * DIM,  ue4, ie4, out, cl_out);
}

// round 17
// speedup vs baseline: 1.1192x; 1.1192x over previous
#include <cuda_runtime.h>
#include <cstdint>

#define NUM_USERS 100000
#define NUM_ITEMS 150000
#define N_NODES   250000
#define DIM       64
#define N_EDGES   2000000
#define EPS_F     0.2f

#define SCAN_B    512
#define N_SCAN_BLK ((N_NODES + SCAN_B - 1) / SCAN_B)   // 489

// ---------------------------------------------------------------------------
// Device scratch (allocation-free, graph-capturable)
// ---------------------------------------------------------------------------
__device__ unsigned g_cnt[N_NODES];        // in-degree per node (build only)
__device__ unsigned g_off[N_NODES + 1];    // CSR row starts (exclusive scan, +sentinel)
__device__ unsigned g_cur[N_NODES];        // fill cursors
__device__ unsigned g_bsum[SCAN_B];        // block sums for the scan
__device__ uint2    g_edges[N_EDGES];      // dst-sorted: {src, val_bits}
__device__ float    g_A[(size_t)N_NODES * DIM];  // x0
__device__ float    g_B[(size_t)N_NODES * DIM];  // x1

// L2-only load (no L1 allocation) for low-reuse random gathers
__device__ __forceinline__ float4 ldcg4(const float4* p) {
    float4 r;
    asm volatile("ld.global.cg.v4.f32 {%0, %1, %2, %3}, [%4];"
                 : "=f"(r.x), "=f"(r.y), "=f"(r.z), "=f"(r.w) : "l"(p));
    return r;
}

// ---------------------------------------------------------------------------
// CSR build
// ---------------------------------------------------------------------------
__global__ void zero_cnt_k() {
    unsigned i = blockIdx.x * blockDim.x + threadIdx.x;
    if (i < N_NODES) { g_cnt[i] = 0u; }
}

__global__ void hist_k(const int* __restrict__ dst) {
    unsigned g = blockIdx.x * blockDim.x + threadIdx.x;
    if (g >= (unsigned)(N_EDGES / 4)) return;
    int4 d4 = __ldg(reinterpret_cast<const int4*>(dst) + g);
    atomicAdd(&g_cnt[d4.x], 1u);
    atomicAdd(&g_cnt[d4.y], 1u);
    atomicAdd(&g_cnt[d4.z], 1u);
    atomicAdd(&g_cnt[d4.w], 1u);
}

__global__ void scan1_k() {
    __shared__ unsigned sm[SCAN_B];
    unsigned i = blockIdx.x * SCAN_B + threadIdx.x;
    unsigned v = (i < N_NODES) ? g_cnt[i] : 0u;
    sm[threadIdx.x] = v;
    __syncthreads();
    for (int ofs = 1; ofs < SCAN_B; ofs <<= 1) {
        unsigned add = (threadIdx.x >= (unsigned)ofs) ? sm[threadIdx.x - ofs] : 0u;
        __syncthreads();
        sm[threadIdx.x] += add;
        __syncthreads();
    }
    unsigned incl = sm[threadIdx.x];
    if (i < N_NODES) g_off[i] = incl - v;            // exclusive within block
    if (threadIdx.x == SCAN_B - 1) g_bsum[blockIdx.x] = incl;
}

__global__ void scan2_k() {
    __shared__ unsigned sm[SCAN_B];
    unsigned v = (threadIdx.x < N_SCAN_BLK) ? g_bsum[threadIdx.x] : 0u;
    sm[threadIdx.x] = v;
    __syncthreads();
    for (int ofs = 1; ofs < SCAN_B; ofs <<= 1) {
        unsigned add = (threadIdx.x >= (unsigned)ofs) ? sm[threadIdx.x - ofs] : 0u;
        __syncthreads();
        sm[threadIdx.x] += add;
        __syncthreads();
    }
    if (threadIdx.x < N_SCAN_BLK) g_bsum[threadIdx.x] = sm[threadIdx.x] - v;  // exclusive
}

__global__ void scan3_k() {
    unsigned i = blockIdx.x * blockDim.x + threadIdx.x;
    if (i >= N_NODES) return;
    unsigned val = g_off[i] + g_bsum[i / SCAN_B];
    g_off[i] = val;
    g_cur[i] = val;
    if (i == 0) g_off[N_NODES] = (unsigned)N_EDGES;   // sentinel
}

__global__ void fill_k(const int* __restrict__ src,
                       const int* __restrict__ dst,
                       const float* __restrict__ vals) {
    unsigned g = blockIdx.x * blockDim.x + threadIdx.x;
    if (g >= (unsigned)(N_EDGES / 4)) return;
    int4   s4 = __ldg(reinterpret_cast<const int4*>(src) + g);
    int4   d4 = __ldg(reinterpret_cast<const int4*>(dst) + g);
    float4 v4 = __ldg(reinterpret_cast<const float4*>(vals) + g);
    unsigned p0 = atomicAdd(&g_cur[d4.x], 1u);
    unsigned p1 = atomicAdd(&g_cur[d4.y], 1u);
    unsigned p2 = atomicAdd(&g_cur[d4.z], 1u);
    unsigned p3 = atomicAdd(&g_cur[d4.w], 1u);
    g_edges[p0] = make_uint2((unsigned)s4.x, __float_as_uint(v4.x));
    g_edges[p1] = make_uint2((unsigned)s4.y, __float_as_uint(v4.y));
    g_edges[p2] = make_uint2((unsigned)s4.z, __float_as_uint(v4.z));
    g_edges[p3] = make_uint2((unsigned)s4.w, __float_as_uint(v4.w));
}

// ---------------------------------------------------------------------------
// Fused layer kernels: gather-reduce + noise perturbation (+ cl / final)
// 16 lanes per node, one float4 column each; unroll-4 over in-edges for MLP.
// Cache policy (measured optimum): edge records __ldg (L1 broadcast reuse
// across lanes + consecutive batches), row gathers ld.global.cg (L2-only,
// ~0.4% L1 hit rate), noise __ldcs / outputs __stcs (one-shot streams).
//   K=0: x0 = f(segsum(E), noise0); A := x0; cl_out = l2norm(x0)
//   K=1: x1 = f(segsum(A), noise1); B := x1
//   K=2: x2 = f(segsum(B), noise2); out = l2norm((e0 + A + B + x2) * 0.25)
// ---------------------------------------------------------------------------
__device__ __forceinline__ float halfwarp_sum(float ss) {
    ss += __shfl_xor_sync(0xffffffffu, ss, 1);
    ss += __shfl_xor_sync(0xffffffffu, ss, 2);
    ss += __shfl_xor_sync(0xffffffffu, ss, 4);
    ss += __shfl_xor_sync(0xffffffffu, ss, 8);
    return ss;
}

template <int K>
__device__ __forceinline__ const float4* src_row(
        unsigned node, const float4* __restrict__ ue, const float4* __restrict__ ie)
{
    if (K == 0) {
        return (node < NUM_USERS) ? (ue + (size_t)node * 16)
                                  : (ie + (size_t)(node - NUM_USERS) * 16);
    }
    const float* b = (K == 1) ? g_A : g_B;
    return reinterpret_cast<const float4*>(b) + (size_t)node * 16;
}

template <int K>
__global__ void __launch_bounds__(256) layer_k(
        const float* __restrict__ noise_k,
        const float4* __restrict__ ue,
        const float4* __restrict__ ie,
        float4* __restrict__ out,      // K==2
        float4* __restrict__ cl_out)   // K==0
{
    unsigned t = blockIdx.x * blockDim.x + threadIdx.x;
    if (t >= (unsigned)N_NODES * 16u) return;
    unsigned node = t >> 4;
    unsigned c = t & 15u;

    unsigned base = __ldg(&g_off[node]);
    unsigned end  = __ldg(&g_off[node + 1]);
    unsigned deg  = end - base;

    float4 s = make_float4(0.f, 0.f, 0.f, 0.f);

    // unroll-4 main loop: 4 independent gathers in flight
    unsigned i = 0;
    for (; i + 4 <= deg; i += 4) {
        uint2 e0 = __ldg(&g_edges[base + i]);
        uint2 e1 = __ldg(&g_edges[base + i + 1]);
        uint2 e2 = __ldg(&g_edges[base + i + 2]);
        uint2 e3 = __ldg(&g_edges[base + i + 3]);
        float4 x0 = ldcg4(src_row<K>(e0.x, ue, ie) + c);
        float4 x1 = ldcg4(src_row<K>(e1.x, ue, ie) + c);
        float4 x2 = ldcg4(src_row<K>(e2.x, ue, ie) + c);
        float4 x3 = ldcg4(src_row<K>(e3.x, ue, ie) + c);
        float v0 = __uint_as_float(e0.y), v1 = __uint_as_float(e1.y);
        float v2 = __uint_as_float(e2.y), v3 = __uint_as_float(e3.y);
        s.x += v0 * x0.x + v1 * x1.x + v2 * x2.x + v3 * x3.x;
        s.y += v0 * x0.y + v1 * x1.y + v2 * x2.y + v3 * x3.y;
        s.z += v0 * x0.z + v1 * x1.z + v2 * x2.z + v3 * x3.z;
        s.w += v0 * x0.w + v1 * x1.w + v2 * x2.w + v3 * x3.w;
    }
    for (; i < deg; i++) {
        uint2 e = __ldg(&g_edges[base + i]);
        float4 x = ldcg4(src_row<K>(e.x, ue, ie) + c);
        float v = __uint_as_float(e.y);
        s.x += v * x.x; s.y += v * x.y; s.z += v * x.z; s.w += v * x.w;
    }

    // noise perturbation
    float4 n4 = __ldcs(reinterpret_cast<const float4*>(noise_k) + t);
    float ss = halfwarp_sum(n4.x * n4.x + n4.y * n4.y + n4.z * n4.z + n4.w * n4.w);
    float scale = rsqrtf(fmaxf(ss, 1e-24f)) * EPS_F;

    float4 x = s;
    x.x += (float)((s.x > 0.f) - (s.x < 0.f)) * n4.x * scale;
    x.y += (float)((s.y > 0.f) - (s.y < 0.f)) * n4.y * scale;
    x.z += (float)((s.z > 0.f) - (s.z < 0.f)) * n4.z * scale;
    x.w += (float)((s.w > 0.f) - (s.w < 0.f)) * n4.w * scale;

    if (K == 2) {
        // fused final: out = l2norm((e0 + x0 + x1 + x2) * 0.25)
        float4 e0 = (node < NUM_USERS)
            ? __ldg(ue + (size_t)node * 16 + c)
            : __ldg(ie + (size_t)(node - NUM_USERS) * 16 + c);
        float4 a0 = reinterpret_cast<const float4*>(g_A)[t];
        float4 a1 = reinterpret_cast<const float4*>(g_B)[t];
        float4 a;
        a.x = (e0.x + a0.x + a1.x + x.x) * 0.25f;
        a.y = (e0.y + a0.y + a1.y + x.y) * 0.25f;
        a.z = (e0.z + a0.z + a1.z + x.z) * 0.25f;
        a.w = (e0.w + a0.w + a1.w + x.w) * 0.25f;
        float s2 = halfwarp_sum(a.x * a.x + a.y * a.y + a.z * a.z + a.w * a.w);
        float inv = rsqrtf(fmaxf(s2, 1e-24f));
        a.x *= inv; a.y *= inv; a.z *= inv; a.w *= inv;
        __stcs(out + t, a);
        return;
    }

    float4* tgt = (K == 0) ? reinterpret_cast<float4*>(g_A)
                           : reinterpret_cast<float4*>(g_B);
    tgt[t] = x;

    if (K == 0) {
        float s2 = halfwarp_sum(x.x * x.x + x.y * x.y + x.z * x.z + x.w * x.w);
        float inv = rsqrtf(fmaxf(s2, 1e-24f));
        x.x *= inv; x.y *= inv; x.z *= inv; x.w *= inv;
        __stcs(cl_out + t, x);
    }
}

extern "C" void kernel_launch(void* const* d_in, const int* in_sizes, int n_in,
                              void* d_out, int out_size) {
    const float* user_emb = (const float*)d_in[0];
    const float* item_emb = (const float*)d_in[1];
    const float* vals     = (const float*)d_in[2];
    const float* noise    = (const float*)d_in[3];
    const int*   src      = (const int*)d_in[4];
    const int*   dst      = (const int*)d_in[5];
    float4* out    = (float4*)d_out;
    float4* cl_out = (float4*)((float*)d_out + (size_t)N_NODES * DIM);
    const float4* ue4 = (const float4*)user_emb;
    const float4* ie4 = (const float4*)item_emb;

    const int TB = 256;
    const int node_blk  = (N_NODES + TB - 1) / TB;                 // 977
    const int edge4_blk = (N_EDGES / 4 + TB - 1) / TB;             // 1954
    const int work_blk  = ((unsigned)N_NODES * 16u + TB - 1) / TB; // 15625

    // CSR build
    zero_cnt_k<<<node_blk, TB>>>();
    hist_k<<<edge4_blk, TB>>>(dst);
    scan1_k<<<N_SCAN_BLK, SCAN_B>>>();
    scan2_k<<<1, SCAN_B>>>();
    scan3_k<<<node_blk, TB>>>();
    fill_k<<<edge4_blk, TB>>>(src, dst, vals);

    // fused layers
    layer_k<0><<<work_blk, TB>>>(noise,                              ue4, ie4, out, cl_out);
    layer_k<1><<<work_blk, TB>>>(noise + (size_t)N_NODES * DIM,      ue4, ie4, out, cl_out);
    layer_k<2><<<work_blk, TB>>>(noise + 2 * (size_t)N_NODES * DIM,  ue4, ie4, out, cl_out);
}